// round 8
// baseline (speedup 1.0000x reference)
#include <cuda_runtime.h>
#include <cuda_bf16.h>

// Problem constants (fixed shapes from reference)
#define BATCH 8
#define CCH   64
#define DD    32
#define HH    64
#define WW    64
#define S_SPATIAL (DD*HH*WW)       // 131072 spatial positions per (b,c)
#define S4        (S_SPATIAL/4)    // 32768 float4 positions

// 8 MB scratch for reduced tensor [B, 2, D, H, W]
__device__ float g_scratch[BATCH * 2 * S_SPATIAL];

// ---------------------------------------------------------------------------
// Kernel 1: channel-wise mean + max over C=64.
// Unroll 16 (16 LDG.128 in flight) + dual accumulators to shorten chains.
// ---------------------------------------------------------------------------
__global__ __launch_bounds__(256) void reduce_mean_max_kernel(const float* __restrict__ x) {
    int idx = blockIdx.x * blockDim.x + threadIdx.x;   // over BATCH * S4
    if (idx >= BATCH * S4) return;
    int b  = idx >> 15;
    int s4 = idx & (S4 - 1);

    const float4* base = reinterpret_cast<const float4*>(x)
                         + (size_t)b * CCH * S4 + s4;

    float4 sumA = make_float4(0.f, 0.f, 0.f, 0.f);
    float4 sumB = make_float4(0.f, 0.f, 0.f, 0.f);
    float4 mxA  = make_float4(-3.4e38f, -3.4e38f, -3.4e38f, -3.4e38f);
    float4 mxB  = mxA;

    #pragma unroll 8
    for (int c = 0; c < CCH; c += 2) {
        float4 t0 = base[(size_t)c * S4];
        float4 t1 = base[(size_t)(c + 1) * S4];
        sumA.x += t0.x; sumA.y += t0.y; sumA.z += t0.z; sumA.w += t0.w;
        sumB.x += t1.x; sumB.y += t1.y; sumB.z += t1.z; sumB.w += t1.w;
        mxA.x = fmaxf(mxA.x, t0.x); mxA.y = fmaxf(mxA.y, t0.y);
        mxA.z = fmaxf(mxA.z, t0.z); mxA.w = fmaxf(mxA.w, t0.w);
        mxB.x = fmaxf(mxB.x, t1.x); mxB.y = fmaxf(mxB.y, t1.y);
        mxB.z = fmaxf(mxB.z, t1.z); mxB.w = fmaxf(mxB.w, t1.w);
    }

    const float inv = 1.0f / (float)CCH;
    float4 avg = make_float4((sumA.x + sumB.x) * inv, (sumA.y + sumB.y) * inv,
                             (sumA.z + sumB.z) * inv, (sumA.w + sumB.w) * inv);
    float4 mx  = make_float4(fmaxf(mxA.x, mxB.x), fmaxf(mxA.y, mxB.y),
                             fmaxf(mxA.z, mxB.z), fmaxf(mxA.w, mxB.w));

    float4* out_avg = reinterpret_cast<float4*>(g_scratch)
                      + (size_t)b * 2 * S4 + s4;
    float4* out_max = out_avg + S4;
    *out_avg = avg;
    *out_max = mx;
}

// ---------------------------------------------------------------------------
// Kernel 2: smem-tiled 3x3x3 SAME conv (2ch -> 1ch) + sigmoid.
// Block (128 thr) tile: 2d x 8h x 64w. Thread: 4w x 2h outputs (8).
// Smem tile [2][4][10][64] (20.5 KB) with pre-zeroed z/y halos.
// Inner loop prefetches the 4 rows of each (ci,dz) group into registers
// (batched LDS, MLP=4), then shuffles, then FMAs.
// __launch_bounds__(128,7) -> ~73-reg budget (occupancy is grid-limited).
// ---------------------------------------------------------------------------
#define TZ 4            // 2 d + 2 halo
#define TY 10           // 8 h + 2 halo
#define TILE_F4 (2*TZ*TY*16)       // 1280 float4

__global__ __launch_bounds__(128, 7) void conv_sigmoid_kernel(const float* __restrict__ Wp,
                                                              float* __restrict__ out) {
    __shared__ __align__(16) float sm_in[2][TZ][TY][WW];   // 20480 B
    __shared__ float sm_w[56];

    const int tid = threadIdx.x;
    const int bx  = blockIdx.x;            // 1024 blocks
    const int ht  = bx & 7;                // 8 h-tiles (8h each)
    const int dt  = (bx >> 3) & 15;        // 16 d-tiles (2d each)
    const int b   = bx >> 7;               // 8 batches
    const int d0  = dt * 2;
    const int h0  = ht * 8;

    // ---- cooperative load: input tile (zero halos) + weights ----
    if (tid < 54) sm_w[tid] = Wp[tid];

    const float* gbase = g_scratch + (size_t)b * 2 * S_SPATIAL;
    #pragma unroll
    for (int i = 0; i < TILE_F4 / 128; i++) {   // 10 iters
        int idx = tid + i * 128;               // 0..1279
        int w16   = idx & 15;
        int rowid = idx >> 4;                  // 0..79
        int y  = rowid % TY;
        int t2 = rowid / TY;                   // 0..7
        int z  = t2 & 3;
        int ci = t2 >> 2;
        int gz = d0 + z - 1;
        int gy = h0 + y - 1;
        float4 v = make_float4(0.f, 0.f, 0.f, 0.f);
        if (gz >= 0 && gz < DD && gy >= 0 && gy < HH) {
            v = *reinterpret_cast<const float4*>(gbase + ci * S_SPATIAL
                                                 + (gz * HH + gy) * WW + w16 * 4);
        }
        *reinterpret_cast<float4*>(&sm_in[ci][z][y][w16 * 4]) = v;
    }
    __syncthreads();

    // ---- thread -> (d_local, h-pair, 4 w) ----
    const int lane   = tid & 31;
    const int lane16 = lane & 15;
    const int w4     = lane16 * 4;
    const int slot   = (tid >> 5) * 2 + (lane >> 4);  // 0..7
    const int dl     = slot >> 2;                     // 0..1
    const int hp     = slot & 3;                      // 0..3
    const int hl0    = hp * 2;                        // local h of first output

    float acc[2][4];
    #pragma unroll
    for (int i = 0; i < 2; i++)
        #pragma unroll
        for (int j = 0; j < 4; j++) acc[i][j] = 0.f;

    #pragma unroll
    for (int ci = 0; ci < 2; ci++) {
        float wreg[27];
        #pragma unroll
        for (int i = 0; i < 27; i++) wreg[i] = sm_w[ci * 27 + i];

        #pragma unroll
        for (int dz = 0; dz < 3; dz++) {
            // Prefetch the 4 rows of this (ci,dz) group (batched LDS.128)
            float4 m[4];
            #pragma unroll
            for (int dyy = 0; dyy < 4; dyy++)
                m[dyy] = *reinterpret_cast<const float4*>(&sm_in[ci][dl + dz][hl0 + dyy][w4]);

            // Halo shuffles for all 4 rows
            float v0[4], v5[4];
            #pragma unroll
            for (int dyy = 0; dyy < 4; dyy++) {
                v0[dyy] = __shfl_up_sync(0xffffffffu, m[dyy].w, 1, 16);
                v5[dyy] = __shfl_down_sync(0xffffffffu, m[dyy].x, 1, 16);
                if (lane16 == 0)  v0[dyy] = 0.f;   // w = -1
                if (lane16 == 15) v5[dyy] = 0.f;   // w = 64
            }

            // FMA block
            #pragma unroll
            for (int dyy = 0; dyy < 4; dyy++) {
                #pragma unroll
                for (int oh = 0; oh < 2; oh++) {
                    const int dy = dyy - oh;          // compile-time
                    if (dy < 0 || dy > 2) continue;   // compile-time prune
                    const float* wr = wreg + dz * 9 + dy * 3;
                    float* a = acc[oh];
                    a[0] = fmaf(v0[dyy], wr[0], fmaf(m[dyy].x, wr[1], fmaf(m[dyy].y, wr[2], a[0])));
                    a[1] = fmaf(m[dyy].x, wr[0], fmaf(m[dyy].y, wr[1], fmaf(m[dyy].z, wr[2], a[1])));
                    a[2] = fmaf(m[dyy].y, wr[0], fmaf(m[dyy].z, wr[1], fmaf(m[dyy].w, wr[2], a[2])));
                    a[3] = fmaf(m[dyy].z, wr[0], fmaf(m[dyy].w, wr[1], fmaf(v5[dyy],  wr[2], a[3])));
                }
            }
        }
    }

    #pragma unroll
    for (int oh = 0; oh < 2; oh++) {
        float4 o;
        o.x = 1.0f / (1.0f + __expf(-acc[oh][0]));
        o.y = 1.0f / (1.0f + __expf(-acc[oh][1]));
        o.z = 1.0f / (1.0f + __expf(-acc[oh][2]));
        o.w = 1.0f / (1.0f + __expf(-acc[oh][3]));
        *reinterpret_cast<float4*>(out + (size_t)b * S_SPATIAL
                                   + ((d0 + dl) * HH + (h0 + hl0 + oh)) * WW + w4) = o;
    }
}

extern "C" void kernel_launch(void* const* d_in, const int* in_sizes, int n_in,
                              void* d_out, int out_size) {
    const float* x  = (const float*)d_in[0];   // [8,64,32,64,64]
    const float* Wp = (const float*)d_in[1];   // [1,2,3,3,3] = 54 floats
    float* out = (float*)d_out;                // [8,1,32,64,64]

    {
        int total = BATCH * S4;                // 262144
        int threads = 256;
        int blocks = (total + threads - 1) / threads;
        reduce_mean_max_kernel<<<blocks, threads>>>(x);
    }
    {
        int blocks = BATCH * 16 * 8;           // 1024
        conv_sigmoid_kernel<<<blocks, 128>>>(Wp, out);
    }
}

// round 9
// speedup vs baseline: 1.2352x; 1.2352x over previous
#include <cuda_runtime.h>
#include <cuda_bf16.h>

// Problem constants (fixed shapes from reference)
#define BATCH 8
#define CCH   64
#define DD    32
#define HH    64
#define WW    64
#define S_SPATIAL (DD*HH*WW)       // 131072 spatial positions per (b,c)
#define S4        (S_SPATIAL/4)    // 32768 float4 positions

// 8 MB scratch for reduced tensor [B, 2, D, H, W]
__device__ float g_scratch[BATCH * 2 * S_SPATIAL];

// ---------------------------------------------------------------------------
// Kernel 1: channel-wise mean + max over C=64.  (R5 version — proven ~42.5us)
// Single accumulator pair, unroll 8: enough MLP without register spills.
// ---------------------------------------------------------------------------
__global__ __launch_bounds__(256) void reduce_mean_max_kernel(const float* __restrict__ x) {
    int idx = blockIdx.x * blockDim.x + threadIdx.x;   // over BATCH * S4
    if (idx >= BATCH * S4) return;
    int b  = idx >> 15;
    int s4 = idx & (S4 - 1);

    const float4* base = reinterpret_cast<const float4*>(x)
                         + (size_t)b * CCH * S4 + s4;

    float4 v = base[0];
    float4 sum = v;
    float4 mx  = v;
    #pragma unroll 8
    for (int c = 1; c < CCH; c++) {
        float4 t = base[(size_t)c * S4];
        sum.x += t.x; sum.y += t.y; sum.z += t.z; sum.w += t.w;
        mx.x = fmaxf(mx.x, t.x); mx.y = fmaxf(mx.y, t.y);
        mx.z = fmaxf(mx.z, t.z); mx.w = fmaxf(mx.w, t.w);
    }
    const float inv = 1.0f / (float)CCH;
    float4 avg = make_float4(sum.x * inv, sum.y * inv, sum.z * inv, sum.w * inv);

    float4* out_avg = reinterpret_cast<float4*>(g_scratch)
                      + (size_t)b * 2 * S4 + s4;
    float4* out_max = out_avg + S4;
    *out_avg = avg;
    *out_max = mx;
}

// ---------------------------------------------------------------------------
// Kernel 2: smem-tiled 3x3x3 SAME conv (2ch -> 1ch) + sigmoid.  (R7 — 9.6us)
// Block (128 thr) tile: 2d x 8h x 64w. Thread: 4w x 2h outputs (8).
// Smem tile [2][4][10][64] (20.5 KB) with pre-zeroed z/y halos.
// __launch_bounds__(128,8) -> 64-reg budget keeps 27 weights in registers.
// ---------------------------------------------------------------------------
#define TZ 4            // 2 d + 2 halo
#define TY 10           // 8 h + 2 halo
#define TILE_F4 (2*TZ*TY*16)       // 1280 float4

__global__ __launch_bounds__(128, 8) void conv_sigmoid_kernel(const float* __restrict__ Wp,
                                                              float* __restrict__ out) {
    __shared__ __align__(16) float sm_in[2][TZ][TY][WW];   // 20480 B
    __shared__ float sm_w[56];

    const int tid = threadIdx.x;
    const int bx  = blockIdx.x;            // 1024 blocks
    const int ht  = bx & 7;                // 8 h-tiles (8h each)
    const int dt  = (bx >> 3) & 15;        // 16 d-tiles (2d each)
    const int b   = bx >> 7;               // 8 batches
    const int d0  = dt * 2;
    const int h0  = ht * 8;

    // ---- cooperative load: input tile (zero halos) + weights ----
    if (tid < 54) sm_w[tid] = Wp[tid];

    const float* gbase = g_scratch + (size_t)b * 2 * S_SPATIAL;
    #pragma unroll
    for (int i = 0; i < TILE_F4 / 128; i++) {   // 10 iters
        int idx = tid + i * 128;               // 0..1279
        int w16   = idx & 15;
        int rowid = idx >> 4;                  // 0..79
        int y  = rowid % TY;
        int t2 = rowid / TY;                   // 0..7
        int z  = t2 & 3;
        int ci = t2 >> 2;
        int gz = d0 + z - 1;
        int gy = h0 + y - 1;
        float4 v = make_float4(0.f, 0.f, 0.f, 0.f);
        if (gz >= 0 && gz < DD && gy >= 0 && gy < HH) {
            v = *reinterpret_cast<const float4*>(gbase + ci * S_SPATIAL
                                                 + (gz * HH + gy) * WW + w16 * 4);
        }
        *reinterpret_cast<float4*>(&sm_in[ci][z][y][w16 * 4]) = v;
    }
    __syncthreads();

    // ---- thread -> (d_local, h-pair, 4 w) ----
    const int lane   = tid & 31;
    const int lane16 = lane & 15;
    const int w4     = lane16 * 4;
    const int slot   = (tid >> 5) * 2 + (lane >> 4);  // 0..7
    const int dl     = slot >> 2;                     // 0..1
    const int hp     = slot & 3;                      // 0..3
    const int hl0    = hp * 2;                        // local h of first output

    float acc[2][4];
    #pragma unroll
    for (int i = 0; i < 2; i++)
        #pragma unroll
        for (int j = 0; j < 4; j++) acc[i][j] = 0.f;

    #pragma unroll
    for (int ci = 0; ci < 2; ci++) {
        float wreg[27];
        #pragma unroll
        for (int i = 0; i < 27; i++) wreg[i] = sm_w[ci * 27 + i];

        #pragma unroll
        for (int dz = 0; dz < 3; dz++) {
            #pragma unroll
            for (int dyy = 0; dyy < 4; dyy++) {       // padded rows hl0+dyy
                float4 m = *reinterpret_cast<const float4*>(&sm_in[ci][dl + dz][hl0 + dyy][w4]);
                float v0 = __shfl_up_sync(0xffffffffu, m.w, 1, 16);
                float v5 = __shfl_down_sync(0xffffffffu, m.x, 1, 16);
                if (lane16 == 0)  v0 = 0.f;   // w = -1 (true boundary)
                if (lane16 == 15) v5 = 0.f;   // w = 64 (true boundary)
                #pragma unroll
                for (int oh = 0; oh < 2; oh++) {
                    const int dy = dyy - oh;          // compile-time
                    if (dy < 0 || dy > 2) continue;   // compile-time prune
                    const float* wr = wreg + dz * 9 + dy * 3;
                    float* a = acc[oh];
                    a[0] = fmaf(v0,  wr[0], fmaf(m.x, wr[1], fmaf(m.y, wr[2], a[0])));
                    a[1] = fmaf(m.x, wr[0], fmaf(m.y, wr[1], fmaf(m.z, wr[2], a[1])));
                    a[2] = fmaf(m.y, wr[0], fmaf(m.z, wr[1], fmaf(m.w, wr[2], a[2])));
                    a[3] = fmaf(m.z, wr[0], fmaf(m.w, wr[1], fmaf(v5,  wr[2], a[3])));
                }
            }
        }
    }

    #pragma unroll
    for (int oh = 0; oh < 2; oh++) {
        float4 o;
        o.x = 1.0f / (1.0f + __expf(-acc[oh][0]));
        o.y = 1.0f / (1.0f + __expf(-acc[oh][1]));
        o.z = 1.0f / (1.0f + __expf(-acc[oh][2]));
        o.w = 1.0f / (1.0f + __expf(-acc[oh][3]));
        *reinterpret_cast<float4*>(out + (size_t)b * S_SPATIAL
                                   + ((d0 + dl) * HH + (h0 + hl0 + oh)) * WW + w4) = o;
    }
}

extern "C" void kernel_launch(void* const* d_in, const int* in_sizes, int n_in,
                              void* d_out, int out_size) {
    const float* x  = (const float*)d_in[0];   // [8,64,32,64,64]
    const float* Wp = (const float*)d_in[1];   // [1,2,3,3,3] = 54 floats
    float* out = (float*)d_out;                // [8,1,32,64,64]

    {
        int total = BATCH * S4;                // 262144
        int threads = 256;
        int blocks = (total + threads - 1) / threads;
        reduce_mean_max_kernel<<<blocks, threads>>>(x);
    }
    {
        int blocks = BATCH * 16 * 8;           // 1024
        conv_sigmoid_kernel<<<blocks, 128>>>(Wp, out);
    }
}